// round 2
// baseline (speedup 1.0000x reference)
#include <cuda_runtime.h>
#include <cstdint>

#define E_DIM 2048
#define T_DIM 2048
#define B_DIM 4
#define D_DIM 1024
#define BT_DIM 8192
#define N_ST 64

// ---------------- scratch (device globals; no allocation allowed) ----------
static __device__ __align__(256) float g_xz [(size_t)BT_DIM * E_DIM];
static __device__ __align__(256) float g_sz [(size_t)BT_DIM * E_DIM];
static __device__ __align__(256) float g_xc [(size_t)BT_DIM * E_DIM];
static __device__ __align__(256) float g_dt [(size_t)BT_DIM * E_DIM];
static __device__ __align__(256) float g_yw [(size_t)BT_DIM * E_DIM];
static __device__ __align__(256) float g_Bp [(size_t)BT_DIM * N_ST];
static __device__ __align__(256) float g_Cp [(size_t)BT_DIM * N_ST];

__device__ __forceinline__ float silu_f(float v) { return v / (1.f + __expf(-v)); }

// ---------------- SGEMM 128x128, BK=8, 256 threads, double buffered --------
// MODE 0: plain store to C0 (row stride N)
// MODE 1: split: cols [0,2048) -> C0 raw ; cols [2048,4096) -> C1 = silu(v),
//         both with row stride 2048
// MODE 2: softplus(v + bias[n]) clipped to [1e-3, 1e-1] -> C0 (row stride N)
template <int MODE>
__global__ __launch_bounds__(256)
void sgemm128(const float* __restrict__ A, const float* __restrict__ Bm,
              float* __restrict__ C0, float* __restrict__ C1,
              const float* __restrict__ bias, int M, int N, int K)
{
    __shared__ float As[2][8][128];
    __shared__ float Bs[2][8][128];
    const int tid = threadIdx.x;
    const int m0 = blockIdx.y * 128;
    const int n0 = blockIdx.x * 128;
    const int arow = tid >> 1, acol = (tid & 1) * 4;
    const int brow = tid >> 5, bcol = (tid & 31) * 4;
    const float* Ap  = A  + (size_t)(m0 + arow) * K + acol;
    const float* Bpp = Bm + (size_t)brow * N + n0 + bcol;

    float4 av = *(const float4*)Ap;
    float4 bv = *(const float4*)Bpp;
    As[0][acol + 0][arow] = av.x; As[0][acol + 1][arow] = av.y;
    As[0][acol + 2][arow] = av.z; As[0][acol + 3][arow] = av.w;
    *(float4*)&Bs[0][brow][bcol] = bv;
    __syncthreads();

    float acc[8][8];
#pragma unroll
    for (int i = 0; i < 8; i++)
#pragma unroll
        for (int j = 0; j < 8; j++) acc[i][j] = 0.f;

    const int tx = tid & 15, ty = tid >> 4;
    const int nt = K >> 3;
    for (int t = 0; t < nt; ++t) {
        const int cur = t & 1;
        if (t + 1 < nt) {
            av = *(const float4*)(Ap + (t + 1) * 8);
            bv = *(const float4*)(Bpp + (size_t)(t + 1) * 8 * N);
        }
#pragma unroll
        for (int k = 0; k < 8; k++) {
            float ar[8], br[8];
            *(float4*)&ar[0] = *(const float4*)&As[cur][k][ty * 8];
            *(float4*)&ar[4] = *(const float4*)&As[cur][k][ty * 8 + 4];
            *(float4*)&br[0] = *(const float4*)&Bs[cur][k][tx * 8];
            *(float4*)&br[4] = *(const float4*)&Bs[cur][k][tx * 8 + 4];
#pragma unroll
            for (int i = 0; i < 8; i++)
#pragma unroll
                for (int j = 0; j < 8; j++)
                    acc[i][j] = fmaf(ar[i], br[j], acc[i][j]);
        }
        if (t + 1 < nt) {
            const int nxt = cur ^ 1;
            __syncthreads();
            As[nxt][acol + 0][arow] = av.x; As[nxt][acol + 1][arow] = av.y;
            As[nxt][acol + 2][arow] = av.z; As[nxt][acol + 3][arow] = av.w;
            *(float4*)&Bs[nxt][brow][bcol] = bv;
            __syncthreads();
        }
    }

    const int ncol = n0 + tx * 8;
    float bf[8];
    if (MODE == 2) {
#pragma unroll
        for (int j = 0; j < 8; j++) bf[j] = bias[ncol + j];
    }
#pragma unroll
    for (int i = 0; i < 8; i++) {
        const int m = m0 + ty * 8 + i;
        if (MODE == 0) {
            *(float4*)(C0 + (size_t)m * N + ncol)     = make_float4(acc[i][0], acc[i][1], acc[i][2], acc[i][3]);
            *(float4*)(C0 + (size_t)m * N + ncol + 4) = make_float4(acc[i][4], acc[i][5], acc[i][6], acc[i][7]);
        } else if (MODE == 1) {
            if (ncol < 2048) {
                *(float4*)(C0 + (size_t)m * 2048 + ncol)     = make_float4(acc[i][0], acc[i][1], acc[i][2], acc[i][3]);
                *(float4*)(C0 + (size_t)m * 2048 + ncol + 4) = make_float4(acc[i][4], acc[i][5], acc[i][6], acc[i][7]);
            } else {
                float s[8];
#pragma unroll
                for (int j = 0; j < 8; j++) s[j] = silu_f(acc[i][j]);
                *(float4*)(C1 + (size_t)m * 2048 + (ncol - 2048))     = make_float4(s[0], s[1], s[2], s[3]);
                *(float4*)(C1 + (size_t)m * 2048 + (ncol - 2048) + 4) = make_float4(s[4], s[5], s[6], s[7]);
            }
        } else {
            float s[8];
#pragma unroll
            for (int j = 0; j < 8; j++) {
                float v = acc[i][j] + bf[j];
                float sp = (v > 15.f) ? v : log1pf(__expf(v));
                s[j] = fminf(fmaxf(sp, 0.001f), 0.1f);
            }
            *(float4*)(C0 + (size_t)m * N + ncol)     = make_float4(s[0], s[1], s[2], s[3]);
            *(float4*)(C0 + (size_t)m * N + ncol + 4) = make_float4(s[4], s[5], s[6], s[7]);
        }
    }
}

// ---------------- B/C projection GEMM: 128x64 tile, K=2048 ------------------
__global__ __launch_bounds__(256)
void sgemm_bc(const float* __restrict__ A, const float* __restrict__ B0,
              const float* __restrict__ B1, float* __restrict__ O0,
              float* __restrict__ O1, int K)
{
    const float* Bm = blockIdx.y ? B1 : B0;
    float* O = blockIdx.y ? O1 : O0;
    __shared__ float As[2][8][128];
    __shared__ float Bs[2][8][64];
    const int tid = threadIdx.x;
    const int m0 = blockIdx.x * 128;
    const int arow = tid >> 1, acol = (tid & 1) * 4;
    const int brow = tid >> 5, bcol = (tid & 31) * 2;
    const float* Ap  = A  + (size_t)(m0 + arow) * K + acol;
    const float* Bpp = Bm + (size_t)brow * 64 + bcol;

    float4 av = *(const float4*)Ap;
    float2 bv = *(const float2*)Bpp;
    As[0][acol + 0][arow] = av.x; As[0][acol + 1][arow] = av.y;
    As[0][acol + 2][arow] = av.z; As[0][acol + 3][arow] = av.w;
    *(float2*)&Bs[0][brow][bcol] = bv;
    __syncthreads();

    float acc[8][4];
#pragma unroll
    for (int i = 0; i < 8; i++)
#pragma unroll
        for (int j = 0; j < 4; j++) acc[i][j] = 0.f;

    const int tx = tid & 15, ty = tid >> 4;
    const int nt = K >> 3;
    for (int t = 0; t < nt; ++t) {
        const int cur = t & 1;
        if (t + 1 < nt) {
            av = *(const float4*)(Ap + (t + 1) * 8);
            bv = *(const float2*)(Bpp + (size_t)(t + 1) * 8 * 64);
        }
#pragma unroll
        for (int k = 0; k < 8; k++) {
            float ar[8], br[4];
            *(float4*)&ar[0] = *(const float4*)&As[cur][k][ty * 8];
            *(float4*)&ar[4] = *(const float4*)&As[cur][k][ty * 8 + 4];
            *(float4*)&br[0] = *(const float4*)&Bs[cur][k][tx * 4];
#pragma unroll
            for (int i = 0; i < 8; i++)
#pragma unroll
                for (int j = 0; j < 4; j++)
                    acc[i][j] = fmaf(ar[i], br[j], acc[i][j]);
        }
        if (t + 1 < nt) {
            const int nxt = cur ^ 1;
            __syncthreads();
            As[nxt][acol + 0][arow] = av.x; As[nxt][acol + 1][arow] = av.y;
            As[nxt][acol + 2][arow] = av.z; As[nxt][acol + 3][arow] = av.w;
            *(float2*)&Bs[nxt][brow][bcol] = bv;
            __syncthreads();
        }
    }
#pragma unroll
    for (int i = 0; i < 8; i++) {
        const int m = m0 + ty * 8 + i;
        *(float4*)(O + (size_t)m * 64 + tx * 4) = make_float4(acc[i][0], acc[i][1], acc[i][2], acc[i][3]);
    }
}

// ---------------- conv along e, weights indexed by t (reference semantics) --
// x_conv[b,t,e] = silu( sum_k x_z[b,t,e-1+k] * W_conv[k,0,t] ), zero pad in e
__global__ __launch_bounds__(256)
void conv_silu_kernel(const float* __restrict__ xz, const float* __restrict__ Wc,
                      float* __restrict__ xc)
{
    __shared__ float s[E_DIM + 4];
    const int row = blockIdx.x;           // b*T + t
    const int t = row & (T_DIM - 1);
    const int tid = threadIdx.x;
    const float* src = xz + (size_t)row * E_DIM;
#pragma unroll
    for (int j = 0; j < E_DIM / 256; ++j)
        s[tid + j * 256 + 1] = src[tid + j * 256];
    if (tid == 0) s[0] = 0.f;
    if (tid < 3) s[E_DIM + 1 + tid] = 0.f;
    __syncthreads();
    const float w0 = Wc[t], w1 = Wc[E_DIM + t], w2 = Wc[2 * E_DIM + t], w3 = Wc[3 * E_DIM + t];
    float* dst = xc + (size_t)row * E_DIM;
#pragma unroll
    for (int j = 0; j < E_DIM / 256; ++j) {
        int e = tid + j * 256;
        float v = w0 * s[e] + w1 * s[e + 1] + w2 * s[e + 2] + w3 * s[e + 3];
        dst[e] = silu_f(v);
    }
}

// ---------------- selective-scan: one warp per (b,e), 2 states/lane ---------
__device__ __forceinline__ float exp_poly(float u) {
    // exp(u) for u in [-0.1, 0]: degree-4 Taylor, abs err <= 8.4e-8
    float r = fmaf(u, 1.f / 24.f, 1.f / 6.f);
    r = fmaf(u, r, 0.5f);
    r = fmaf(u, r, 1.f);
    r = fmaf(u, r, 1.f);
    return r;
}

__global__ __launch_bounds__(512)
void scan_kernel(const float* __restrict__ xc, const float* __restrict__ dt,
                 const float* __restrict__ Bp, const float* __restrict__ Cp,
                 const float* __restrict__ sz, const float* __restrict__ A_log,
                 float* __restrict__ yw)
{
    __shared__ float sB[2][N_ST], sC[2][N_ST];
    const int tid  = threadIdx.x;
    const int warp = tid >> 5, lane = tid & 31;
    const int eg = blockIdx.x & 127;
    const int b  = blockIdx.x >> 7;
    const int e  = eg * 16 + warp;
    const size_t base   = ((size_t)b * T_DIM) * E_DIM + e;   // (b, t=0, e)
    const size_t bcbase = ((size_t)b * T_DIM) * N_ST;

    const float A0 = -__expf(A_log[2 * lane]);
    const float A1 = -__expf(A_log[2 * lane + 1]);

    if (tid < N_ST)            sB[0][tid]         = Bp[bcbase + tid];
    else if (tid < 2 * N_ST)   sC[0][tid - N_ST]  = Cp[bcbase + tid - N_ST];
    __syncthreads();

    float h0 = 0.f, h1 = 0.f;
    for (int t = 0; t < T_DIM; ++t) {
        const int cur = t & 1;
        float rB = 0.f, rC = 0.f;
        if (t + 1 < T_DIM) {
            const size_t nb = bcbase + (size_t)(t + 1) * N_ST;
            if (tid < N_ST)          rB = Bp[nb + tid];
            else if (tid < 2 * N_ST) rC = Cp[nb + tid - N_ST];
        }
        const float xv  = xc[base + (size_t)t * E_DIM];
        const float dtv = dt[base + (size_t)t * E_DIM];
        const float szv = sz[base + (size_t)t * E_DIM];

        const float dA0 = exp_poly(dtv * A0);
        const float dA1 = exp_poly(dtv * A1);
        const float dtx = dtv * xv;
        const float2 Bv = *(const float2*)&sB[cur][2 * lane];
        const float2 Cv = *(const float2*)&sC[cur][2 * lane];
        h0 = fmaf(dA0, h0, dtx * Bv.x);
        h1 = fmaf(dA1, h1, dtx * Bv.y);
        float y = fmaf(h0, Cv.x, h1 * Cv.y);

        y += __shfl_xor_sync(0xFFFFFFFFu, y, 16);
        y += __shfl_xor_sync(0xFFFFFFFFu, y, 8);
        y += __shfl_xor_sync(0xFFFFFFFFu, y, 4);
        y += __shfl_xor_sync(0xFFFFFFFFu, y, 2);
        y += __shfl_xor_sync(0xFFFFFFFFu, y, 1);
        if (lane == 0) yw[base + (size_t)t * E_DIM] = y * szv;

        if (t + 1 < T_DIM) {
            const int nxt = cur ^ 1;
            if (tid < N_ST)          sB[nxt][tid]        = rB;
            else if (tid < 2 * N_ST) sC[nxt][tid - N_ST] = rC;
        }
        __syncthreads();
    }
}

// ---------------------------------------------------------------------------
extern "C" void kernel_launch(void* const* d_in, const int* in_sizes, int n_in,
                              void* d_out, int out_size)
{
    (void)in_sizes; (void)n_in; (void)out_size;
    const float* x      = (const float*)d_in[0];
    const float* W_in   = (const float*)d_in[1];
    const float* W_conv = (const float*)d_in[2];
    const float* W_dt   = (const float*)d_in[3];
    const float* b_dt   = (const float*)d_in[4];
    const float* W_B    = (const float*)d_in[5];
    const float* W_C    = (const float*)d_in[6];
    const float* A_log  = (const float*)d_in[7];
    const float* W_out  = (const float*)d_in[8];
    float* out = (float*)d_out;

    float *xz, *sz, *xc, *dtb, *yw, *Bp, *Cp;
    cudaGetSymbolAddress((void**)&xz,  g_xz);
    cudaGetSymbolAddress((void**)&sz,  g_sz);
    cudaGetSymbolAddress((void**)&xc,  g_xc);
    cudaGetSymbolAddress((void**)&dtb, g_dt);
    cudaGetSymbolAddress((void**)&yw,  g_yw);
    cudaGetSymbolAddress((void**)&Bp,  g_Bp);
    cudaGetSymbolAddress((void**)&Cp,  g_Cp);

    // 1) in-projection: [8192,1024] @ [1024,4096] -> xz (raw) / sz (silu)
    sgemm128<1><<<dim3(4096 / 128, BT_DIM / 128), 256>>>(
        x, W_in, xz, sz, nullptr, BT_DIM, 2 * E_DIM, D_DIM);

    // 2) conv along e (weights indexed by t) + silu
    conv_silu_kernel<<<BT_DIM, 256>>>(xz, W_conv, xc);

    // 3) dt projection + softplus + clip: [8192,2048] @ [2048,2048]
    sgemm128<2><<<dim3(E_DIM / 128, BT_DIM / 128), 256>>>(
        xc, W_dt, dtb, nullptr, b_dt, BT_DIM, E_DIM, E_DIM);

    // 4) B/C projections: [8192,2048] @ [2048,64]
    sgemm_bc<<<dim3(BT_DIM / 128, 2), 256>>>(xc, W_B, W_C, Bp, Cp, E_DIM);

    // 5) selective scan (fuses y * silu(z))
    scan_kernel<<<B_DIM * (E_DIM / 16), 512>>>(xc, dtb, Bp, Cp, sz, A_log, yw);

    // 6) out projection: [8192,2048] @ [2048,1024] -> d_out
    sgemm128<0><<<dim3(D_DIM / 128, BT_DIM / 128), 256>>>(
        yw, W_out, out, nullptr, nullptr, BT_DIM, D_DIM, E_DIM);
}

// round 4
// speedup vs baseline: 1.0485x; 1.0485x over previous
#include <cuda_runtime.h>
#include <cuda_bf16.h>
#include <cstdint>

#define E_DIM 2048
#define T_DIM 2048
#define B_DIM 4
#define D_DIM 1024
#define BT_DIM 8192
#define N_ST 64

typedef __nv_bfloat16 bf16;

// ---------------- scratch (device globals; no allocation allowed) ----------
static __device__ __align__(1024) float g_xz [(size_t)BT_DIM * E_DIM];
static __device__ __align__(1024) float g_sz [(size_t)BT_DIM * E_DIM];
static __device__ __align__(1024) float g_xc [(size_t)BT_DIM * E_DIM];
static __device__ __align__(1024) float g_dt [(size_t)BT_DIM * E_DIM];
static __device__ __align__(1024) float g_Bp [(size_t)BT_DIM * N_ST];
static __device__ __align__(1024) float g_Cp [(size_t)BT_DIM * N_ST];
// bf16 hi/lo splits (activations)
static __device__ __align__(1024) bf16 g_xh  [(size_t)BT_DIM * D_DIM];
static __device__ __align__(1024) bf16 g_xl  [(size_t)BT_DIM * D_DIM];
static __device__ __align__(1024) bf16 g_xch [(size_t)BT_DIM * E_DIM];
static __device__ __align__(1024) bf16 g_xcl [(size_t)BT_DIM * E_DIM];
static __device__ __align__(1024) bf16 g_ywh [(size_t)BT_DIM * E_DIM];
static __device__ __align__(1024) bf16 g_ywl [(size_t)BT_DIM * E_DIM];
// bf16 hi/lo transposed weights [N,K]
static __device__ __align__(1024) bf16 g_WinTh [(size_t)4096 * 1024];
static __device__ __align__(1024) bf16 g_WinTl [(size_t)4096 * 1024];
static __device__ __align__(1024) bf16 g_WdtTh [(size_t)2048 * 2048];
static __device__ __align__(1024) bf16 g_WdtTl [(size_t)2048 * 2048];
static __device__ __align__(1024) bf16 g_WoutTh[(size_t)1024 * 2048];
static __device__ __align__(1024) bf16 g_WoutTl[(size_t)1024 * 2048];
static __device__ __align__(1024) bf16 g_WbcH  [(size_t)128 * 2048];
static __device__ __align__(1024) bf16 g_WbcL  [(size_t)128 * 2048];

__device__ __forceinline__ float silu_f(float v) { return v / (1.f + __expf(-v)); }

// ---------------- PTX helpers ----------------------------------------------
__device__ __forceinline__ uint32_t s2u(const void* p) {
    uint32_t a;
    asm("{ .reg .u64 t; cvta.to.shared.u64 t, %1; cvt.u32.u64 %0, t; }" : "=r"(a) : "l"(p));
    return a;
}
__device__ __forceinline__ uint32_t sw128(uint32_t off) { return off ^ ((off >> 3) & 0x70); }

#define CPA16(dst, src) asm volatile("cp.async.cg.shared.global [%0], [%1], 16;" :: "r"(dst), "l"(src))
#define CPA_COMMIT()    asm volatile("cp.async.commit_group;" ::: "memory")
#define CPA_WAIT1()     asm volatile("cp.async.wait_group 1;" ::: "memory")
#define CPA_WAIT0()     asm volatile("cp.async.wait_group 0;" ::: "memory")

__device__ __forceinline__ void ldsm4(uint32_t r[4], uint32_t a) {
    asm volatile("ldmatrix.sync.aligned.m8n8.x4.shared.b16 {%0,%1,%2,%3}, [%4];"
        : "=r"(r[0]), "=r"(r[1]), "=r"(r[2]), "=r"(r[3]) : "r"(a));
}
__device__ __forceinline__ void mma_bf16(float c[4], const uint32_t a[4],
                                         uint32_t b0, uint32_t b1) {
    asm volatile(
        "mma.sync.aligned.m16n8k16.row.col.f32.bf16.bf16.f32 "
        "{%0,%1,%2,%3}, {%4,%5,%6,%7}, {%8,%9}, {%0,%1,%2,%3};"
        : "+f"(c[0]), "+f"(c[1]), "+f"(c[2]), "+f"(c[3])
        : "r"(a[0]), "r"(a[1]), "r"(a[2]), "r"(a[3]), "r"(b0), "r"(b1));
}

// ---------------- HMMA bf16x3 GEMM: C[M,N] = A[M,K] * W[K,N] ---------------
// A as hi/lo bf16 [M,K] row-major; W as hi/lo bf16 [N,K] (pre-transposed).
// CTA 128x128, BK=64, 8 warps (2x4), warp tile 64x32, double-buffered cp.async.
// MODE 0: plain fp32 store, stride N
// MODE 1: N=4096 logical; cols<2048 -> C0 raw, cols>=2048 -> C1 = silu, stride 2048
// MODE 2: softplus(v + bias[col]) clipped [1e-3,1e-1], stride N
// MODE 3: N=128; cols<64 -> C0, else C1, both stride 64
#define GEMM_SMEM (2 * 4 * 16384)

template <int MODE>
__global__ __launch_bounds__(256)
void gemm_mma(const bf16* __restrict__ Ah, const bf16* __restrict__ Al,
              const bf16* __restrict__ Bh, const bf16* __restrict__ Bl,
              float* __restrict__ C0, float* __restrict__ C1,
              const float* __restrict__ bias, int M, int N, int K)
{
    extern __shared__ __align__(1024) char smem[];
    const uint32_t su = s2u(smem);
    const int tid = threadIdx.x;
    const int wid = tid >> 5, lane = tid & 31;
    const int wm = wid & 1, wn = wid >> 1;     // 2 x 4 warp grid
    const int n0 = blockIdx.x * 128;
    const int m0 = blockIdx.y * 128;
    const int NT = K >> 6;

    const bf16* srcs[4] = { Ah + (size_t)m0 * K, Al + (size_t)m0 * K,
                            Bh + (size_t)n0 * K, Bl + (size_t)n0 * K };

    auto load_stage = [&](int st, int kc) {
        const uint32_t sbase = su + st * 65536;
#pragma unroll
        for (int w = 0; w < 4; w++) {
            const bf16* g0 = srcs[w] + kc * 64;
#pragma unroll
            for (int i = 0; i < 4; i++) {
                int c = tid + i * 256;
                int row = c >> 3, ch = c & 7;
                const bf16* g = g0 + (size_t)row * K + ch * 8;
                uint32_t s = sbase + w * 16384 + sw128(row * 128 + ch * 16);
                CPA16(s, g);
            }
        }
        CPA_COMMIT();
    };

    float acc[4][4][4];
#pragma unroll
    for (int a = 0; a < 4; a++)
#pragma unroll
        for (int b = 0; b < 4; b++)
#pragma unroll
            for (int c = 0; c < 4; c++) acc[a][b][c] = 0.f;

    load_stage(0, 0);

    const int arow = lane & 15;
    const int khalf = lane >> 4;

    for (int t = 0; t < NT; ++t) {
        if (t + 1 < NT) { load_stage((t + 1) & 1, t + 1); CPA_WAIT1(); }
        else             CPA_WAIT0();
        __syncthreads();

        const uint32_t sb = su + (t & 1) * 65536;
#pragma unroll
        for (int kk = 0; kk < 4; kk++) {
            const int kb = kk * 32 + khalf * 16;
            uint32_t aH[4][4], aL[4][4], bH[2][4], bL[2][4];
#pragma unroll
            for (int mt = 0; mt < 4; mt++) {
                int r = wm * 64 + mt * 16 + arow;
                ldsm4(aH[mt], sb +         sw128(r * 128 + kb));
                ldsm4(aL[mt], sb + 16384 + sw128(r * 128 + kb));
            }
#pragma unroll
            for (int nt = 0; nt < 2; nt++) {
                int r = wn * 32 + nt * 16 + arow;
                ldsm4(bH[nt], sb + 32768 + sw128(r * 128 + kb));
                ldsm4(bL[nt], sb + 49152 + sw128(r * 128 + kb));
            }
#pragma unroll
            for (int mt = 0; mt < 4; mt++)
#pragma unroll
                for (int j = 0; j < 4; j++) {
                    const int g = j >> 1, o = j & 1;
                    mma_bf16(acc[mt][j], aH[mt], bH[g][o], bH[g][o + 2]);
                    mma_bf16(acc[mt][j], aH[mt], bL[g][o], bL[g][o + 2]);
                    mma_bf16(acc[mt][j], aL[mt], bH[g][o], bH[g][o + 2]);
                }
        }
        __syncthreads();
    }

    // ---------------- epilogue from registers -------------------------------
    const int rbase = m0 + wm * 64 + (lane >> 2);
    const int cbase = n0 + wn * 32 + (lane & 3) * 2;
#pragma unroll
    for (int mt = 0; mt < 4; mt++) {
#pragma unroll
        for (int j = 0; j < 4; j++) {
            const int col = cbase + j * 8;
#pragma unroll
            for (int half = 0; half < 2; half++) {
                const int m = rbase + mt * 16 + half * 8;
                float v0 = acc[mt][j][half * 2];
                float v1 = acc[mt][j][half * 2 + 1];
                if (MODE == 0) {
                    *(float2*)(C0 + (size_t)m * N + col) = make_float2(v0, v1);
                } else if (MODE == 1) {
                    if (n0 < 2048)
                        *(float2*)(C0 + (size_t)m * 2048 + col) = make_float2(v0, v1);
                    else
                        *(float2*)(C1 + (size_t)m * 2048 + (col - 2048)) =
                            make_float2(silu_f(v0), silu_f(v1));
                } else if (MODE == 2) {
                    float u0 = v0 + bias[col], u1 = v1 + bias[col + 1];
                    float s0 = (u0 > 15.f) ? u0 : log1pf(__expf(u0));
                    float s1 = (u1 > 15.f) ? u1 : log1pf(__expf(u1));
                    s0 = fminf(fmaxf(s0, 0.001f), 0.1f);
                    s1 = fminf(fmaxf(s1, 0.001f), 0.1f);
                    *(float2*)(C0 + (size_t)m * N + col) = make_float2(s0, s1);
                } else {
                    if (col < 64)
                        *(float2*)(C0 + (size_t)m * 64 + col) = make_float2(v0, v1);
                    else
                        *(float2*)(C1 + (size_t)m * 64 + (col - 64)) = make_float2(v0, v1);
                }
            }
        }
    }
}

// ---------------- weight transpose + bf16 hi/lo split -----------------------
__global__ __launch_bounds__(256)
void tsplit_kernel(const float* __restrict__ in, bf16* __restrict__ oh,
                   bf16* __restrict__ ol, int K, int N)
{
    __shared__ float tile[32][33];
    const int n0 = blockIdx.x * 32, k0 = blockIdx.y * 32;
    const int tx = threadIdx.x & 31, ty = threadIdx.x >> 5;
#pragma unroll
    for (int i = 0; i < 4; i++)
        tile[ty + i * 8][tx] = in[(size_t)(k0 + ty + i * 8) * N + n0 + tx];
    __syncthreads();
#pragma unroll
    for (int i = 0; i < 4; i++) {
        float v = tile[tx][ty + i * 8];
        bf16 h = __float2bfloat16(v);
        float lo = v - __bfloat162float(h);
        size_t o = (size_t)(n0 + ty + i * 8) * K + k0 + tx;
        oh[o] = h;
        ol[o] = __float2bfloat16(lo);
    }
}

// ---------------- x split ----------------------------------------------------
__global__ __launch_bounds__(512)
void xsplit_kernel(const float* __restrict__ x, bf16* __restrict__ oh, bf16* __restrict__ ol)
{
    size_t i = (size_t)blockIdx.x * 512 + threadIdx.x;
    float v = x[i];
    bf16 h = __float2bfloat16(v);
    oh[i] = h;
    ol[i] = __float2bfloat16(v - __bfloat162float(h));
}

// ---------------- conv along e, weights indexed by t, + silu + split --------
__global__ __launch_bounds__(256)
void conv_silu_kernel(const float* __restrict__ xz, const float* __restrict__ Wc,
                      float* __restrict__ xc, bf16* __restrict__ xch, bf16* __restrict__ xcl)
{
    __shared__ float s[E_DIM + 4];
    const int row = blockIdx.x;           // b*T + t
    const int t = row & (T_DIM - 1);
    const int tid = threadIdx.x;
    const float* src = xz + (size_t)row * E_DIM;
#pragma unroll
    for (int j = 0; j < E_DIM / 256; ++j)
        s[tid + j * 256 + 1] = src[tid + j * 256];
    if (tid == 0) s[0] = 0.f;
    if (tid < 3) s[E_DIM + 1 + tid] = 0.f;
    __syncthreads();
    const float w0 = Wc[t], w1 = Wc[E_DIM + t], w2 = Wc[2 * E_DIM + t], w3 = Wc[3 * E_DIM + t];
    const size_t base = (size_t)row * E_DIM;
#pragma unroll
    for (int j = 0; j < E_DIM / 256; ++j) {
        int e = tid + j * 256;
        float v = w0 * s[e] + w1 * s[e + 1] + w2 * s[e + 2] + w3 * s[e + 3];
        float sv = silu_f(v);
        xc[base + e] = sv;
        bf16 h = __float2bfloat16(sv);
        xch[base + e] = h;
        xcl[base + e] = __float2bfloat16(sv - __bfloat162float(h));
    }
}

// ---------------- selective-scan: one warp per (b,e), 2 states/lane ---------
__device__ __forceinline__ float exp_poly(float u) {
    float r = fmaf(u, 1.f / 24.f, 1.f / 6.f);
    r = fmaf(u, r, 0.5f);
    r = fmaf(u, r, 1.f);
    r = fmaf(u, r, 1.f);
    return r;
}

__global__ __launch_bounds__(512)
void scan_kernel(const float* __restrict__ xc, const float* __restrict__ dt,
                 const float* __restrict__ Bp, const float* __restrict__ Cp,
                 const float* __restrict__ sz, const float* __restrict__ A_log,
                 bf16* __restrict__ ywh, bf16* __restrict__ ywl)
{
    __shared__ float sB[2][N_ST], sC[2][N_ST];
    const int tid  = threadIdx.x;
    const int warp = tid >> 5, lane = tid & 31;
    const int eg = blockIdx.x & 127;
    const int b  = blockIdx.x >> 7;
    const int e  = eg * 16 + warp;
    const size_t base   = ((size_t)b * T_DIM) * E_DIM + e;
    const size_t bcbase = ((size_t)b * T_DIM) * N_ST;

    const float A0 = -__expf(A_log[2 * lane]);
    const float A1 = -__expf(A_log[2 * lane + 1]);

    if (tid < N_ST)            sB[0][tid]        = Bp[bcbase + tid];
    else if (tid < 2 * N_ST)   sC[0][tid - N_ST] = Cp[bcbase + tid - N_ST];
    __syncthreads();

    float h0 = 0.f, h1 = 0.f;
    for (int t = 0; t < T_DIM; ++t) {
        const int cur = t & 1;
        float rB = 0.f, rC = 0.f;
        if (t + 1 < T_DIM) {
            const size_t nb = bcbase + (size_t)(t + 1) * N_ST;
            if (tid < N_ST)          rB = Bp[nb + tid];
            else if (tid < 2 * N_ST) rC = Cp[nb + tid - N_ST];
        }
        const float xv  = xc[base + (size_t)t * E_DIM];
        const float dtv = dt[base + (size_t)t * E_DIM];
        const float szv = sz[base + (size_t)t * E_DIM];

        const float dA0 = exp_poly(dtv * A0);
        const float dA1 = exp_poly(dtv * A1);
        const float dtx = dtv * xv;
        const float2 Bv = *(const float2*)&sB[cur][2 * lane];
        const float2 Cv = *(const float2*)&sC[cur][2 * lane];
        h0 = fmaf(dA0, h0, dtx * Bv.x);
        h1 = fmaf(dA1, h1, dtx * Bv.y);
        float y = fmaf(h0, Cv.x, h1 * Cv.y);

        y += __shfl_xor_sync(0xFFFFFFFFu, y, 16);
        y += __shfl_xor_sync(0xFFFFFFFFu, y, 8);
        y += __shfl_xor_sync(0xFFFFFFFFu, y, 4);
        y += __shfl_xor_sync(0xFFFFFFFFu, y, 2);
        y += __shfl_xor_sync(0xFFFFFFFFu, y, 1);
        if (lane == 0) {
            float yv = y * szv;
            bf16 h = __float2bfloat16(yv);
            ywh[base + (size_t)t * E_DIM] = h;
            ywl[base + (size_t)t * E_DIM] = __float2bfloat16(yv - __bfloat162float(h));
        }

        if (t + 1 < T_DIM) {
            const int nxt = cur ^ 1;
            if (tid < N_ST)          sB[nxt][tid]        = rB;
            else if (tid < 2 * N_ST) sC[nxt][tid - N_ST] = rC;
        }
        __syncthreads();
    }
}

// ---------------------------------------------------------------------------
extern "C" void kernel_launch(void* const* d_in, const int* in_sizes, int n_in,
                              void* d_out, int out_size)
{
    (void)in_sizes; (void)n_in; (void)out_size;
    const float* x      = (const float*)d_in[0];
    const float* W_in   = (const float*)d_in[1];
    const float* W_conv = (const float*)d_in[2];
    const float* W_dt   = (const float*)d_in[3];
    const float* b_dt   = (const float*)d_in[4];
    const float* W_B    = (const float*)d_in[5];
    const float* W_C    = (const float*)d_in[6];
    const float* A_log  = (const float*)d_in[7];
    const float* W_out  = (const float*)d_in[8];
    float* out = (float*)d_out;

    float *xz, *sz, *xc, *dtb, *Bpp, *Cpp;
    bf16 *xh, *xl, *xch, *xcl, *ywh, *ywl;
    bf16 *WinTh, *WinTl, *WdtTh, *WdtTl, *WoutTh, *WoutTl, *WbcH, *WbcL;
    cudaGetSymbolAddress((void**)&xz,  g_xz);
    cudaGetSymbolAddress((void**)&sz,  g_sz);
    cudaGetSymbolAddress((void**)&xc,  g_xc);
    cudaGetSymbolAddress((void**)&dtb, g_dt);
    cudaGetSymbolAddress((void**)&Bpp, g_Bp);
    cudaGetSymbolAddress((void**)&Cpp, g_Cp);
    cudaGetSymbolAddress((void**)&xh,  g_xh);
    cudaGetSymbolAddress((void**)&xl,  g_xl);
    cudaGetSymbolAddress((void**)&xch, g_xch);
    cudaGetSymbolAddress((void**)&xcl, g_xcl);
    cudaGetSymbolAddress((void**)&ywh, g_ywh);
    cudaGetSymbolAddress((void**)&ywl, g_ywl);
    cudaGetSymbolAddress((void**)&WinTh,  g_WinTh);
    cudaGetSymbolAddress((void**)&WinTl,  g_WinTl);
    cudaGetSymbolAddress((void**)&WdtTh,  g_WdtTh);
    cudaGetSymbolAddress((void**)&WdtTl,  g_WdtTl);
    cudaGetSymbolAddress((void**)&WoutTh, g_WoutTh);
    cudaGetSymbolAddress((void**)&WoutTl, g_WoutTl);
    cudaGetSymbolAddress((void**)&WbcH,   g_WbcH);
    cudaGetSymbolAddress((void**)&WbcL,   g_WbcL);

    cudaFuncSetAttribute(gemm_mma<0>, cudaFuncAttributeMaxDynamicSharedMemorySize, GEMM_SMEM);
    cudaFuncSetAttribute(gemm_mma<1>, cudaFuncAttributeMaxDynamicSharedMemorySize, GEMM_SMEM);
    cudaFuncSetAttribute(gemm_mma<2>, cudaFuncAttributeMaxDynamicSharedMemorySize, GEMM_SMEM);
    cudaFuncSetAttribute(gemm_mma<3>, cudaFuncAttributeMaxDynamicSharedMemorySize, GEMM_SMEM);

    // 0) prep: split x, transpose+split weights
    xsplit_kernel<<<(BT_DIM * D_DIM) / 512, 512>>>(x, xh, xl);
    tsplit_kernel<<<dim3(4096 / 32, 1024 / 32), 256>>>(W_in,  WinTh,  WinTl,  1024, 4096);
    tsplit_kernel<<<dim3(2048 / 32, 2048 / 32), 256>>>(W_dt,  WdtTh,  WdtTl,  2048, 2048);
    tsplit_kernel<<<dim3(1024 / 32, 2048 / 32), 256>>>(W_out, WoutTh, WoutTl, 2048, 1024);
    tsplit_kernel<<<dim3(64 / 32, 2048 / 32), 256>>>(W_B, WbcH,             WbcL,             2048, 64);
    tsplit_kernel<<<dim3(64 / 32, 2048 / 32), 256>>>(W_C, WbcH + 64 * 2048, WbcL + 64 * 2048, 2048, 64);

    // 1) in-projection: [8192,1024] @ [1024,4096] -> xz raw / sz silu
    gemm_mma<1><<<dim3(4096 / 128, BT_DIM / 128), 256, GEMM_SMEM>>>(
        xh, xl, WinTh, WinTl, xz, sz, nullptr, BT_DIM, 4096, 1024);

    // 2) conv along e + silu + bf16 split
    conv_silu_kernel<<<BT_DIM, 256>>>(xz, W_conv, xc, xch, xcl);

    // 3) dt projection + softplus + clip
    gemm_mma<2><<<dim3(E_DIM / 128, BT_DIM / 128), 256, GEMM_SMEM>>>(
        xch, xcl, WdtTh, WdtTl, dtb, nullptr, b_dt, BT_DIM, E_DIM, E_DIM);

    // 4) B/C projections (fused into one N=128 GEMM)
    gemm_mma<3><<<dim3(1, BT_DIM / 128), 256, GEMM_SMEM>>>(
        xch, xcl, WbcH, WbcL, Bpp, Cpp, nullptr, BT_DIM, 128, 2048);

    // 5) selective scan (fuses y * silu(z), emits bf16 hi/lo)
    scan_kernel<<<B_DIM * (E_DIM / 16), 512>>>(xc, dtb, Bpp, Cpp, sz, A_log, ywh, ywl);

    // 6) out projection -> d_out
    gemm_mma<0><<<dim3(D_DIM / 128, BT_DIM / 128), 256, GEMM_SMEM>>>(
        ywh, ywl, WoutTh, WoutTl, out, nullptr, nullptr, BT_DIM, D_DIM, E_DIM);
}

// round 5
// speedup vs baseline: 1.8753x; 1.7885x over previous
#include <cuda_runtime.h>
#include <cuda_bf16.h>
#include <cstdint>

#define E_DIM 2048
#define T_DIM 2048
#define B_DIM 4
#define D_DIM 1024
#define BT_DIM 8192
#define N_ST 64

typedef __nv_bfloat16 bf16;
typedef unsigned long long u64;

// ---------------- scratch (device globals; no allocation allowed) ----------
static __device__ __align__(1024) float g_xz [(size_t)BT_DIM * E_DIM];
static __device__ __align__(1024) float g_sz [(size_t)BT_DIM * E_DIM];
static __device__ __align__(1024) float g_xc [(size_t)BT_DIM * E_DIM];
static __device__ __align__(1024) float g_dt [(size_t)BT_DIM * E_DIM];
static __device__ __align__(1024) float g_Bp [(size_t)BT_DIM * N_ST];
static __device__ __align__(1024) float g_Cp [(size_t)BT_DIM * N_ST];
// bf16 hi/lo splits (activations)
static __device__ __align__(1024) bf16 g_xh  [(size_t)BT_DIM * D_DIM];
static __device__ __align__(1024) bf16 g_xl  [(size_t)BT_DIM * D_DIM];
static __device__ __align__(1024) bf16 g_xch [(size_t)BT_DIM * E_DIM];
static __device__ __align__(1024) bf16 g_xcl [(size_t)BT_DIM * E_DIM];
static __device__ __align__(1024) bf16 g_ywh [(size_t)BT_DIM * E_DIM];
static __device__ __align__(1024) bf16 g_ywl [(size_t)BT_DIM * E_DIM];
// bf16 hi/lo transposed weights [N,K]
static __device__ __align__(1024) bf16 g_WinTh [(size_t)4096 * 1024];
static __device__ __align__(1024) bf16 g_WinTl [(size_t)4096 * 1024];
static __device__ __align__(1024) bf16 g_WdtTh [(size_t)2048 * 2048];
static __device__ __align__(1024) bf16 g_WdtTl [(size_t)2048 * 2048];
static __device__ __align__(1024) bf16 g_WoutTh[(size_t)1024 * 2048];
static __device__ __align__(1024) bf16 g_WoutTl[(size_t)1024 * 2048];
static __device__ __align__(1024) bf16 g_WbcH  [(size_t)128 * 2048];
static __device__ __align__(1024) bf16 g_WbcL  [(size_t)128 * 2048];

__device__ __forceinline__ float silu_f(float v) { return v / (1.f + __expf(-v)); }

// ---------------- PTX helpers ----------------------------------------------
__device__ __forceinline__ uint32_t s2u(const void* p) {
    uint32_t a;
    asm("{ .reg .u64 t; cvta.to.shared.u64 t, %1; cvt.u32.u64 %0, t; }" : "=r"(a) : "l"(p));
    return a;
}
__device__ __forceinline__ uint32_t sw128(uint32_t off) { return off ^ ((off >> 3) & 0x70); }

#define CPA16(dst, src) asm volatile("cp.async.cg.shared.global [%0], [%1], 16;" :: "r"(dst), "l"(src))
#define CPA_COMMIT()    asm volatile("cp.async.commit_group;" ::: "memory")
#define CPA_WAIT1()     asm volatile("cp.async.wait_group 1;" ::: "memory")
#define CPA_WAIT0()     asm volatile("cp.async.wait_group 0;" ::: "memory")

__device__ __forceinline__ void ldsm4(uint32_t r[4], uint32_t a) {
    asm volatile("ldmatrix.sync.aligned.m8n8.x4.shared.b16 {%0,%1,%2,%3}, [%4];"
        : "=r"(r[0]), "=r"(r[1]), "=r"(r[2]), "=r"(r[3]) : "r"(a));
}
__device__ __forceinline__ void mma_bf16(float c[4], const uint32_t a[4],
                                         uint32_t b0, uint32_t b1) {
    asm volatile(
        "mma.sync.aligned.m16n8k16.row.col.f32.bf16.bf16.f32 "
        "{%0,%1,%2,%3}, {%4,%5,%6,%7}, {%8,%9}, {%0,%1,%2,%3};"
        : "+f"(c[0]), "+f"(c[1]), "+f"(c[2]), "+f"(c[3])
        : "r"(a[0]), "r"(a[1]), "r"(a[2]), "r"(a[3]), "r"(b0), "r"(b1));
}

// packed f32x2 (base sm_100+ feature, works on compute_103)
__device__ __forceinline__ u64 pk2(float x, float y) {
    u64 r; asm("mov.b64 %0,{%1,%2};" : "=l"(r) : "f"(x), "f"(y)); return r;
}
__device__ __forceinline__ void unpk2(float& x, float& y, u64 v) {
    asm("mov.b64 {%0,%1}, %2;" : "=f"(x), "=f"(y) : "l"(v));
}
__device__ __forceinline__ u64 f2fma(u64 a, u64 b, u64 c) {
    u64 d; asm("fma.rn.f32x2 %0,%1,%2,%3;" : "=l"(d) : "l"(a), "l"(b), "l"(c)); return d;
}
__device__ __forceinline__ u64 f2mul(u64 a, u64 b) {
    u64 d; asm("mul.rn.f32x2 %0,%1,%2;" : "=l"(d) : "l"(a), "l"(b)); return d;
}

// ---------------- HMMA bf16x3 GEMM: C[M,N] = A[M,K] * W[K,N] ---------------
// A as hi/lo bf16 [M,K] row-major; W as hi/lo bf16 [N,K] (pre-transposed).
// CTA 128x128, BK=64, 16 warps (4x4), warp tile 32x32, double-buffered cp.async.
// MODE 0: plain fp32 store, stride N
// MODE 1: N=4096 logical; cols<2048 -> C0 raw, cols>=2048 -> C1 = silu, stride 2048
// MODE 2: softplus(v + bias[col]) clipped [1e-3,1e-1], stride N
// MODE 3: N=128; cols<64 -> C0, else C1, both stride 64
#define GEMM_SMEM (2 * 4 * 16384)

template <int MODE>
__global__ __launch_bounds__(512)
void gemm_mma(const bf16* __restrict__ Ah, const bf16* __restrict__ Al,
              const bf16* __restrict__ Bh, const bf16* __restrict__ Bl,
              float* __restrict__ C0, float* __restrict__ C1,
              const float* __restrict__ bias, int M, int N, int K)
{
    extern __shared__ __align__(1024) char smem[];
    const uint32_t su = s2u(smem);
    const int tid = threadIdx.x;
    const int wid = tid >> 5, lane = tid & 31;
    const int wm = wid & 3, wn = wid >> 2;     // 4 x 4 warp grid
    const int n0 = blockIdx.x * 128;
    const int m0 = blockIdx.y * 128;
    const int NT = K >> 6;

    const bf16* srcs[4] = { Ah + (size_t)m0 * K, Al + (size_t)m0 * K,
                            Bh + (size_t)n0 * K, Bl + (size_t)n0 * K };

    auto load_stage = [&](int st, int kc) {
        const uint32_t sbase = su + st * 65536;
#pragma unroll
        for (int w = 0; w < 4; w++) {
            const bf16* g0 = srcs[w] + kc * 64;
#pragma unroll
            for (int i = 0; i < 2; i++) {
                int c = tid + i * 512;
                int row = c >> 3, ch = c & 7;
                const bf16* g = g0 + (size_t)row * K + ch * 8;
                uint32_t s = sbase + w * 16384 + sw128(row * 128 + ch * 16);
                CPA16(s, g);
            }
        }
        CPA_COMMIT();
    };

    float acc[2][4][4];
#pragma unroll
    for (int a = 0; a < 2; a++)
#pragma unroll
        for (int b = 0; b < 4; b++)
#pragma unroll
            for (int c = 0; c < 4; c++) acc[a][b][c] = 0.f;

    load_stage(0, 0);

    const int arow = lane & 15;
    const int khalf = lane >> 4;

    for (int t = 0; t < NT; ++t) {
        if (t + 1 < NT) { load_stage((t + 1) & 1, t + 1); CPA_WAIT1(); }
        else             CPA_WAIT0();
        __syncthreads();

        const uint32_t sb = su + (t & 1) * 65536;
#pragma unroll
        for (int kk = 0; kk < 4; kk++) {
            const int kb = kk * 32 + khalf * 16;
            uint32_t aH[2][4], aL[2][4], bH[2][4], bL[2][4];
#pragma unroll
            for (int mt = 0; mt < 2; mt++) {
                int r = wm * 32 + mt * 16 + arow;
                ldsm4(aH[mt], sb +         sw128(r * 128 + kb));
                ldsm4(aL[mt], sb + 16384 + sw128(r * 128 + kb));
            }
#pragma unroll
            for (int bt = 0; bt < 2; bt++) {
                int r = wn * 32 + bt * 16 + arow;
                ldsm4(bH[bt], sb + 32768 + sw128(r * 128 + kb));
                ldsm4(bL[bt], sb + 49152 + sw128(r * 128 + kb));
            }
#pragma unroll
            for (int mt = 0; mt < 2; mt++)
#pragma unroll
                for (int bt = 0; bt < 2; bt++)
#pragma unroll
                    for (int o = 0; o < 2; o++) {
                        const int j = bt * 2 + o;
                        mma_bf16(acc[mt][j], aH[mt], bH[bt][o], bH[bt][o + 2]);
                        mma_bf16(acc[mt][j], aH[mt], bL[bt][o], bL[bt][o + 2]);
                        mma_bf16(acc[mt][j], aL[mt], bH[bt][o], bH[bt][o + 2]);
                    }
        }
        __syncthreads();
    }

    // ---------------- epilogue from registers -------------------------------
    const int rbase = m0 + wm * 32 + (lane >> 2);
    const int cbase = n0 + wn * 32 + (lane & 3) * 2;
#pragma unroll
    for (int mt = 0; mt < 2; mt++) {
#pragma unroll
        for (int j = 0; j < 4; j++) {
            const int col = cbase + j * 8;
#pragma unroll
            for (int half = 0; half < 2; half++) {
                const int m = rbase + mt * 16 + half * 8;
                float v0 = acc[mt][j][half * 2];
                float v1 = acc[mt][j][half * 2 + 1];
                if (MODE == 0) {
                    *(float2*)(C0 + (size_t)m * N + col) = make_float2(v0, v1);
                } else if (MODE == 1) {
                    if (n0 < 2048)
                        *(float2*)(C0 + (size_t)m * 2048 + col) = make_float2(v0, v1);
                    else
                        *(float2*)(C1 + (size_t)m * 2048 + (col - 2048)) =
                            make_float2(silu_f(v0), silu_f(v1));
                } else if (MODE == 2) {
                    float u0 = v0 + bias[col], u1 = v1 + bias[col + 1];
                    float s0 = (u0 > 15.f) ? u0 : log1pf(__expf(u0));
                    float s1 = (u1 > 15.f) ? u1 : log1pf(__expf(u1));
                    s0 = fminf(fmaxf(s0, 0.001f), 0.1f);
                    s1 = fminf(fmaxf(s1, 0.001f), 0.1f);
                    *(float2*)(C0 + (size_t)m * N + col) = make_float2(s0, s1);
                } else {
                    if (col < 64)
                        *(float2*)(C0 + (size_t)m * 64 + col) = make_float2(v0, v1);
                    else
                        *(float2*)(C1 + (size_t)m * 64 + (col - 64)) = make_float2(v0, v1);
                }
            }
        }
    }
}

// ---------------- weight transpose + bf16 hi/lo split -----------------------
__global__ __launch_bounds__(256)
void tsplit_kernel(const float* __restrict__ in, bf16* __restrict__ oh,
                   bf16* __restrict__ ol, int K, int N)
{
    __shared__ float tile[32][33];
    const int n0 = blockIdx.x * 32, k0 = blockIdx.y * 32;
    const int tx = threadIdx.x & 31, ty = threadIdx.x >> 5;
#pragma unroll
    for (int i = 0; i < 4; i++)
        tile[ty + i * 8][tx] = in[(size_t)(k0 + ty + i * 8) * N + n0 + tx];
    __syncthreads();
#pragma unroll
    for (int i = 0; i < 4; i++) {
        float v = tile[tx][ty + i * 8];
        bf16 h = __float2bfloat16(v);
        float lo = v - __bfloat162float(h);
        size_t o = (size_t)(n0 + ty + i * 8) * K + k0 + tx;
        oh[o] = h;
        ol[o] = __float2bfloat16(lo);
    }
}

// ---------------- x split ----------------------------------------------------
__global__ __launch_bounds__(512)
void xsplit_kernel(const float* __restrict__ x, bf16* __restrict__ oh, bf16* __restrict__ ol)
{
    size_t i = (size_t)blockIdx.x * 512 + threadIdx.x;
    float v = x[i];
    bf16 h = __float2bfloat16(v);
    oh[i] = h;
    ol[i] = __float2bfloat16(v - __bfloat162float(h));
}

// ---------------- conv along e, weights indexed by t, + silu + split --------
__global__ __launch_bounds__(256)
void conv_silu_kernel(const float* __restrict__ xz, const float* __restrict__ Wc,
                      float* __restrict__ xc, bf16* __restrict__ xch, bf16* __restrict__ xcl)
{
    __shared__ float s[E_DIM + 4];
    const int row = blockIdx.x;           // b*T + t
    const int t = row & (T_DIM - 1);
    const int tid = threadIdx.x;
    const float* src = xz + (size_t)row * E_DIM;
#pragma unroll
    for (int j = 0; j < E_DIM / 256; ++j)
        s[tid + j * 256 + 1] = src[tid + j * 256];
    if (tid == 0) s[0] = 0.f;
    if (tid < 3) s[E_DIM + 1 + tid] = 0.f;
    __syncthreads();
    const float w0 = Wc[t], w1 = Wc[E_DIM + t], w2 = Wc[2 * E_DIM + t], w3 = Wc[3 * E_DIM + t];
    const size_t base = (size_t)row * E_DIM;
#pragma unroll
    for (int j = 0; j < E_DIM / 256; ++j) {
        int e = tid + j * 256;
        float v = w0 * s[e] + w1 * s[e + 1] + w2 * s[e + 2] + w3 * s[e + 3];
        float sv = silu_f(v);
        xc[base + e] = sv;
        bf16 h = __float2bfloat16(sv);
        xch[base + e] = h;
        xcl[base + e] = __float2bfloat16(sv - __bfloat162float(h));
    }
}

// ---------------- selective scan: warp per (b,e), f32x2 packed, decoupled ---
// 512 threads = 16 warps = 16 consecutive e per block. Output staged in smem
// and flushed every 32 steps as coalesced rows.
__global__ __launch_bounds__(512)
void scan_kernel(const float* __restrict__ xc, const float* __restrict__ dt,
                 const float* __restrict__ Bp, const float* __restrict__ Cp,
                 const float* __restrict__ sz, const float* __restrict__ A_log,
                 bf16* __restrict__ ywh, bf16* __restrict__ ywl)
{
    __shared__ float sty[32][17];       // [t mod 32][warp] staged y*silu(z)
    const int tid  = threadIdx.x;
    const int warp = tid >> 5, lane = tid & 31;
    const int e0 = (blockIdx.x & 127) * 16;
    const int b  = blockIdx.x >> 7;
    const int e  = e0 + warp;
    const size_t base   = ((size_t)b * T_DIM) * E_DIM + e;
    const size_t bcbase = ((size_t)b * T_DIM) * N_ST + 2 * lane;

    const float A0 = -__expf(A_log[2 * lane]);
    const float A1 = -__expf(A_log[2 * lane + 1]);
    const u64 A2 = pk2(A0, A1);
    const u64 C24 = pk2(1.f / 24.f, 1.f / 24.f);
    const u64 C6  = pk2(1.f / 6.f, 1.f / 6.f);
    const u64 C05 = pk2(0.5f, 0.5f);
    const u64 C1  = pk2(1.f, 1.f);

    // prefetched values for step t
    float xv  = xc[base];
    float dtv = dt[base];
    float szv = sz[base];
    float2 Bv = *(const float2*)(Bp + bcbase);
    float2 Cv = *(const float2*)(Cp + bcbase);

    u64 h = 0;
    for (int t = 0; t < T_DIM; ++t) {
        // prefetch step t+1 (clamped)
        const int tn = (t + 1 < T_DIM) ? (t + 1) : t;
        const float xn  = xc[base + (size_t)tn * E_DIM];
        const float dtn = dt[base + (size_t)tn * E_DIM];
        const float szn = sz[base + (size_t)tn * E_DIM];
        const float2 Bn = *(const float2*)(Bp + bcbase + (size_t)tn * N_ST);
        const float2 Cn = *(const float2*)(Cp + bcbase + (size_t)tn * N_ST);

        // dA = exp(dt*A) via degree-4 poly (dt*A in [-0.1, 0])
        const u64 dt2 = pk2(dtv, dtv);
        u64 u = f2mul(dt2, A2);
        u64 r = f2fma(u, C24, C6);
        r = f2fma(u, r, C05);
        r = f2fma(u, r, C1);
        r = f2fma(u, r, C1);
        const float dtx = dtv * xv;
        const u64 dtx2 = pk2(dtx, dtx);
        const u64 Bv2 = pk2(Bv.x, Bv.y);
        const u64 Cv2 = pk2(Cv.x, Cv.y);
        h = f2fma(r, h, f2mul(dtx2, Bv2));
        const u64 yp = f2mul(h, Cv2);
        float y0, y1;
        unpk2(y0, y1, yp);
        float y = y0 + y1;
        y += __shfl_xor_sync(0xFFFFFFFFu, y, 16);
        y += __shfl_xor_sync(0xFFFFFFFFu, y, 8);
        y += __shfl_xor_sync(0xFFFFFFFFu, y, 4);
        y += __shfl_xor_sync(0xFFFFFFFFu, y, 2);
        y += __shfl_xor_sync(0xFFFFFFFFu, y, 1);
        if (lane == 0) sty[t & 31][warp] = y * szv;

        xv = xn; dtv = dtn; szv = szn; Bv = Bn; Cv = Cn;

        if ((t & 31) == 31) {
            __syncthreads();
            // flush rows t-31..t : thread -> (row = tid>>4, col = tid&15)
            const int row = tid >> 4, col = tid & 15;
            const float yv = sty[row][col];
            const bf16 hh = __float2bfloat16(yv);
            const bf16 ll = __float2bfloat16(yv - __bfloat162float(hh));
            const size_t o = ((size_t)b * T_DIM + (t - 31 + row)) * E_DIM + e0 + col;
            ywh[o] = hh;
            ywl[o] = ll;
            __syncthreads();
        }
    }
}

// ---------------------------------------------------------------------------
extern "C" void kernel_launch(void* const* d_in, const int* in_sizes, int n_in,
                              void* d_out, int out_size)
{
    (void)in_sizes; (void)n_in; (void)out_size;
    const float* x      = (const float*)d_in[0];
    const float* W_in   = (const float*)d_in[1];
    const float* W_conv = (const float*)d_in[2];
    const float* W_dt   = (const float*)d_in[3];
    const float* b_dt   = (const float*)d_in[4];
    const float* W_B    = (const float*)d_in[5];
    const float* W_C    = (const float*)d_in[6];
    const float* A_log  = (const float*)d_in[7];
    const float* W_out  = (const float*)d_in[8];
    float* out = (float*)d_out;

    float *xz, *sz, *xc, *dtb, *Bpp, *Cpp;
    bf16 *xh, *xl, *xch, *xcl, *ywh, *ywl;
    bf16 *WinTh, *WinTl, *WdtTh, *WdtTl, *WoutTh, *WoutTl, *WbcH, *WbcL;
    cudaGetSymbolAddress((void**)&xz,  g_xz);
    cudaGetSymbolAddress((void**)&sz,  g_sz);
    cudaGetSymbolAddress((void**)&xc,  g_xc);
    cudaGetSymbolAddress((void**)&dtb, g_dt);
    cudaGetSymbolAddress((void**)&Bpp, g_Bp);
    cudaGetSymbolAddress((void**)&Cpp, g_Cp);
    cudaGetSymbolAddress((void**)&xh,  g_xh);
    cudaGetSymbolAddress((void**)&xl,  g_xl);
    cudaGetSymbolAddress((void**)&xch, g_xch);
    cudaGetSymbolAddress((void**)&xcl, g_xcl);
    cudaGetSymbolAddress((void**)&ywh, g_ywh);
    cudaGetSymbolAddress((void**)&ywl, g_ywl);
    cudaGetSymbolAddress((void**)&WinTh,  g_WinTh);
    cudaGetSymbolAddress((void**)&WinTl,  g_WinTl);
    cudaGetSymbolAddress((void**)&WdtTh,  g_WdtTh);
    cudaGetSymbolAddress((void**)&WdtTl,  g_WdtTl);
    cudaGetSymbolAddress((void**)&WoutTh, g_WoutTh);
    cudaGetSymbolAddress((void**)&WoutTl, g_WoutTl);
    cudaGetSymbolAddress((void**)&WbcH,   g_WbcH);
    cudaGetSymbolAddress((void**)&WbcL,   g_WbcL);

    cudaFuncSetAttribute(gemm_mma<0>, cudaFuncAttributeMaxDynamicSharedMemorySize, GEMM_SMEM);
    cudaFuncSetAttribute(gemm_mma<1>, cudaFuncAttributeMaxDynamicSharedMemorySize, GEMM_SMEM);
    cudaFuncSetAttribute(gemm_mma<2>, cudaFuncAttributeMaxDynamicSharedMemorySize, GEMM_SMEM);
    cudaFuncSetAttribute(gemm_mma<3>, cudaFuncAttributeMaxDynamicSharedMemorySize, GEMM_SMEM);

    // 0) prep: split x, transpose+split weights
    xsplit_kernel<<<(BT_DIM * D_DIM) / 512, 512>>>(x, xh, xl);
    tsplit_kernel<<<dim3(4096 / 32, 1024 / 32), 256>>>(W_in,  WinTh,  WinTl,  1024, 4096);
    tsplit_kernel<<<dim3(2048 / 32, 2048 / 32), 256>>>(W_dt,  WdtTh,  WdtTl,  2048, 2048);
    tsplit_kernel<<<dim3(1024 / 32, 2048 / 32), 256>>>(W_out, WoutTh, WoutTl, 2048, 1024);
    tsplit_kernel<<<dim3(64 / 32, 2048 / 32), 256>>>(W_B, WbcH,             WbcL,             2048, 64);
    tsplit_kernel<<<dim3(64 / 32, 2048 / 32), 256>>>(W_C, WbcH + 64 * 2048, WbcL + 64 * 2048, 2048, 64);

    // 1) in-projection: [8192,1024] @ [1024,4096] -> xz raw / sz silu
    gemm_mma<1><<<dim3(4096 / 128, BT_DIM / 128), 512, GEMM_SMEM>>>(
        xh, xl, WinTh, WinTl, xz, sz, nullptr, BT_DIM, 4096, 1024);

    // 2) conv along e + silu + bf16 split
    conv_silu_kernel<<<BT_DIM, 256>>>(xz, W_conv, xc, xch, xcl);

    // 3) dt projection + softplus + clip
    gemm_mma<2><<<dim3(E_DIM / 128, BT_DIM / 128), 512, GEMM_SMEM>>>(
        xch, xcl, WdtTh, WdtTl, dtb, nullptr, b_dt, BT_DIM, E_DIM, E_DIM);

    // 4) B/C projections (fused into one N=128 GEMM)
    gemm_mma<3><<<dim3(1, BT_DIM / 128), 512, GEMM_SMEM>>>(
        xch, xcl, WbcH, WbcL, Bpp, Cpp, nullptr, BT_DIM, 128, 2048);

    // 5) selective scan (fuses y * silu(z), emits bf16 hi/lo)
    scan_kernel<<<B_DIM * (E_DIM / 16), 512>>>(xc, dtb, Bpp, Cpp, sz, A_log, ywh, ywl);

    // 6) out projection -> d_out
    gemm_mma<0><<<dim3(D_DIM / 128, BT_DIM / 128), 512, GEMM_SMEM>>>(
        ywh, ywl, WoutTh, WoutTl, out, nullptr, nullptr, BT_DIM, D_DIM, E_DIM);
}